// round 12
// baseline (speedup 1.0000x reference)
#include <cuda_runtime.h>
#include <cuda_fp16.h>
#include <math.h>
#include <float.h>

#define NMAX 100000
#define EMAX 1600000
#define CDIM 40

typedef unsigned long long u64;

// ---------------------------------------------------------------------------
// Scratch (device globals; tail kernel restores zero-state each call)
// ---------------------------------------------------------------------------
__device__ __align__(16) float  g_h1[NMAX * 64];
__device__ __align__(16) float  g_h2[NMAX * 64];
__device__ __align__(16) __half g_y [NMAX * 64];  // fp16 neighbor-transformed feats
__device__ __align__(16) float  g_z [NMAX * 64];  // fp32 self part (+bias)
__device__ int g_deg[NMAX];
__device__ int g_cur[NMAX];
__device__ int g_startArr[NMAX];
__device__ int g_pref[1024];
__device__ int g_colArr[EMAX];

// ---------------------------------------------------------------------------
// f32x2 packed-FMA helpers
// ---------------------------------------------------------------------------
__device__ __forceinline__ u64 pack2(float lo, float hi) {
    u64 r;
    asm("mov.b64 %0, {%1, %2};" : "=l"(r) : "f"(lo), "f"(hi));
    return r;
}
__device__ __forceinline__ void fma2(u64& d, u64 a, u64 b) {
    asm("fma.rn.f32x2 %0, %1, %2, %0;" : "+l"(d) : "l"(a), "l"(b));
}
__device__ __forceinline__ float hsum2(u64 v) {
    float lo, hi;
    asm("mov.b64 {%0, %1}, %2;" : "=f"(lo), "=f"(hi) : "l"(v));
    return lo + hi;
}

// ---------------------------------------------------------------------------
// Launch 1: degree histogram (deg starts zeroed)
// ---------------------------------------------------------------------------
__global__ void hist_kernel(const int* __restrict__ dst, int* __restrict__ deg, int E) {
    int e = blockIdx.x * blockDim.x + threadIdx.x;
    if (e < E) atomicAdd(&deg[dst[e]], 1);
}

// ---------------------------------------------------------------------------
// Launch 2: single-pass exclusive scan, decoupled lookback (98 blocks, 1 wave)
// ---------------------------------------------------------------------------
__global__ void scan_kernel(const int* __restrict__ deg, int* __restrict__ start,
                            int* __restrict__ pref, int n) {
    const int t = threadIdx.x, b = blockIdx.x;
    const int gid = b * 1024 + t;
    const int v = (gid < n) ? deg[gid] : 0;
    const int lane = t & 31, w = t >> 5;
    int inc = v;
#pragma unroll
    for (int o = 1; o < 32; o <<= 1) {
        int u = __shfl_up_sync(0xffffffffu, inc, o);
        if (lane >= o) inc += u;
    }
    __shared__ int ws[32];
    __shared__ int sPref;
    if (lane == 31) ws[w] = inc;
    __syncthreads();
    if (t < 32) {
        int s = ws[t];
#pragma unroll
        for (int o = 1; o < 32; o <<= 1) {
            int u = __shfl_up_sync(0xffffffffu, s, o);
            if (t >= o) s += u;
        }
        ws[t] = s;
    }
    __syncthreads();
    const int offs  = (w > 0) ? ws[w - 1] : 0;
    const int total = ws[31];
    if (t == 0) {
        int prefix = 0;
        if (b > 0) {
            while ((prefix = atomicAdd(&pref[b], 0)) == 0) __nanosleep(40);
            prefix -= 1;
        }
        atomicExch(&pref[b + 1], prefix + total + 1);
        sPref = prefix;
    }
    __syncthreads();
    if (gid < n) start[gid] = sPref + offs + inc - v;
}

// ---------------------------------------------------------------------------
// Launch 3: CSR fill (cur starts zeroed)
// ---------------------------------------------------------------------------
__global__ void fill_kernel(const int* __restrict__ src, const int* __restrict__ dst,
                            const int* __restrict__ start, int* __restrict__ cur,
                            int* __restrict__ col, int E) {
    int e = blockIdx.x * blockDim.x + threadIdx.x;
    if (e < E) {
        int d = dst[e];
        int p = start[d] + atomicAdd(&cur[d], 1);
        col[p] = src[e];
    }
}

// ---------------------------------------------------------------------------
// Dual dense transform: y = fp16(x@Wl^T), z = x@Wr^T + b
// Tile = 64 nodes, 256 threads; warp g owns nodes g*8..g*8+7, lane = j (&j+32).
// Per kp: 4 distinct weight LDS.64 (8cyc) + 8 broadcast row LDS.64 (8cyc)
// feed 32 fma2  => crossbar ratio 0.5 cyc/fma2 (was 0.75).
// Dynamic SMEM 48KB exactly: sWl 16K | sWr 16K | sX 16K.
// ---------------------------------------------------------------------------
template <int OUTS>
__launch_bounds__(256)
__global__ void gemm_dual_kernel(const float4* __restrict__ xin4,
                                 const float* __restrict__ Wl,
                                 const float* __restrict__ Wr,
                                 const float* __restrict__ bias,
                                 __half* __restrict__ y, float* __restrict__ z, int nN) {
    extern __shared__ __align__(16) unsigned char smem[];
    u64*   sWl = (u64*)smem;
    u64*   sWr = (u64*)(smem + 16384);
    float* sX  = (float*)(smem + 32768);   // 64 rows x 64 floats

    const int tid = threadIdx.x;
    for (int idx = tid; idx < 2048; idx += 256) {
        int kp = idx >> 6, j = idx & 63;
        float l0 = 0.f, l1 = 0.f, r0 = 0.f, r1 = 0.f;
        if (j < OUTS) {
            l0 = Wl[j * 64 + 2 * kp]; l1 = Wl[j * 64 + 2 * kp + 1];
            r0 = Wr[j * 64 + 2 * kp]; r1 = Wr[j * 64 + 2 * kp + 1];
        }
        sWl[idx] = pack2(l0, l1);
        sWr[idx] = pack2(r0, r1);
    }

    const int j   = tid & 31;
    const int g   = tid >> 5;        // warp id: owns nodes g*8..g*8+7
    const int gn2 = tid >> 2;        // stage: row 0..63
    const int q2  = tid & 3;         // stage: chunks q2, q2+4, q2+8, q2+12
    const float bj0 = (j < OUTS) ? __ldg(&bias[j]) : 0.f;
    const float bj1 = (j + 32 < OUTS) ? __ldg(&bias[j + 32]) : 0.f;
    const bool  hi  = (j + 32 < OUTS);

    const int nTiles = (nN + 63) >> 6;
    for (int t = blockIdx.x; t < nTiles; t += gridDim.x) {
        __syncthreads();
        const int base = t << 6;

        // Stage 64 rows (4 float4 per thread)
        {
            const int node = base + gn2;
            float4 v0 = {0,0,0,0}, v1 = {0,0,0,0}, v2 = {0,0,0,0}, v3 = {0,0,0,0};
            if (node < nN) {
                const float4* rs = xin4 + (size_t)node * 16 + q2;
                v0 = __ldg(rs); v1 = __ldg(rs + 4); v2 = __ldg(rs + 8); v3 = __ldg(rs + 12);
            }
            float4* dx = (float4*)sX + gn2 * 16;
            dx[q2] = v0; dx[q2 + 4] = v1; dx[q2 + 8] = v2; dx[q2 + 12] = v3;
        }
        __syncthreads();

        u64 ay0[8], ay1[8], az0[8], az1[8];
#pragma unroll
        for (int n = 0; n < 8; n++) { ay0[n] = 0; ay1[n] = 0; az0[n] = 0; az1[n] = 0; }

        const u64* pX = (const u64*)sX + (g * 8) * 32;

#pragma unroll 2
        for (int kp = 0; kp < 32; kp++) {
            u64 wl0 = sWl[kp * 64 + j];
            u64 wl1 = sWl[kp * 64 + j + 32];
            u64 wr0 = sWr[kp * 64 + j];
            u64 wr1 = sWr[kp * 64 + j + 32];
#pragma unroll
            for (int n = 0; n < 8; n++) {
                u64 xv = pX[n * 32 + kp];
                fma2(ay0[n], xv, wl0);
                fma2(ay1[n], xv, wl1);
                fma2(az0[n], xv, wr0);
                fma2(az1[n], xv, wr1);
            }
        }

#pragma unroll
        for (int n = 0; n < 8; n++) {
            const int node = base + g * 8 + n;
            if (node < nN) {
                y[(size_t)node * OUTS + j] = __float2half(hsum2(ay0[n]));
                z[(size_t)node * OUTS + j] = hsum2(az0[n]) + bj0;
                if (hi) {
                    y[(size_t)node * OUTS + j + 32] = __float2half(hsum2(ay1[n]));
                    z[(size_t)node * OUTS + j + 32] = hsum2(az1[n]) + bj1;
                }
            }
        }
    }
}

// ---------------------------------------------------------------------------
// fp16 gather helpers
// ---------------------------------------------------------------------------
__device__ __forceinline__ void acc8(float* a, uint4 v) {
    float2 f;
    f = __half22float2(*(const __half2*)&v.x); a[0] += f.x; a[1] += f.y;
    f = __half22float2(*(const __half2*)&v.y); a[2] += f.x; a[3] += f.y;
    f = __half22float2(*(const __half2*)&v.z); a[4] += f.x; a[5] += f.y;
    f = __half22float2(*(const __half2*)&v.w); a[6] += f.x; a[7] += f.y;
}

// ---------------------------------------------------------------------------
// Gather (hidden layers, OUTS=64): out = relu(mean y + z)
// ---------------------------------------------------------------------------
__launch_bounds__(256)
__global__ void gather64_kernel(const __half* __restrict__ y,
                                const float* __restrict__ z,
                                const int* __restrict__ start,
                                const int* __restrict__ deg,
                                const int* __restrict__ col,
                                float* __restrict__ out, int nN) {
    const int node = blockIdx.x * 32 + (threadIdx.x >> 3);
    const int q = threadIdx.x & 7;
    if (node >= nN) return;

    const int d  = __ldg(&deg[node]);
    const int p0 = __ldg(&start[node]);

    float a[8] = {0.f,0.f,0.f,0.f,0.f,0.f,0.f,0.f};
    int i = 0;
    for (; i + 4 <= d; i += 4) {
        int n0 = __ldg(&col[p0 + i]);
        int n1 = __ldg(&col[p0 + i + 1]);
        int n2 = __ldg(&col[p0 + i + 2]);
        int n3 = __ldg(&col[p0 + i + 3]);
        uint4 v0 = __ldg((const uint4*)(y + (size_t)n0 * 64) + q);
        uint4 v1 = __ldg((const uint4*)(y + (size_t)n1 * 64) + q);
        uint4 v2 = __ldg((const uint4*)(y + (size_t)n2 * 64) + q);
        uint4 v3 = __ldg((const uint4*)(y + (size_t)n3 * 64) + q);
        acc8(a, v0); acc8(a, v1); acc8(a, v2); acc8(a, v3);
    }
    for (; i < d; i++) {
        int n0 = __ldg(&col[p0 + i]);
        uint4 v0 = __ldg((const uint4*)(y + (size_t)n0 * 64) + q);
        acc8(a, v0);
    }

    const float iv = 1.0f / fmaxf((float)d, 1.0f);
    const float* zr = z + (size_t)node * 64 + q * 8;
    float4 zc0 = __ldg((const float4*)zr);
    float4 zc1 = __ldg((const float4*)(zr + 4));
    float4 r0, r1;
    r0.x = fmaxf(a[0] * iv + zc0.x, 0.f); r0.y = fmaxf(a[1] * iv + zc0.y, 0.f);
    r0.z = fmaxf(a[2] * iv + zc0.z, 0.f); r0.w = fmaxf(a[3] * iv + zc0.w, 0.f);
    r1.x = fmaxf(a[4] * iv + zc1.x, 0.f); r1.y = fmaxf(a[5] * iv + zc1.y, 0.f);
    r1.z = fmaxf(a[6] * iv + zc1.z, 0.f); r1.w = fmaxf(a[7] * iv + zc1.w, 0.f);
    float* orow = out + (size_t)node * 64 + q * 8;
    *(float4*)orow       = r0;
    *(float4*)(orow + 4) = r1;
}

// ---------------------------------------------------------------------------
// Final gather + fused log_softmax (OUTS=40, 5 active chunks of 8).
// All 32 lanes stay alive for the 8-lane shfl reductions.
// ---------------------------------------------------------------------------
__launch_bounds__(256)
__global__ void gather_lsm_kernel(const __half* __restrict__ y,
                                  const float* __restrict__ z,
                                  const int* __restrict__ start,
                                  const int* __restrict__ deg,
                                  const int* __restrict__ col,
                                  float* __restrict__ out, int nN) {
    const int node = blockIdx.x * 32 + (threadIdx.x >> 3);
    const int q = threadIdx.x & 7;
    const bool valid = (node < nN) && (q < 5);

    int d = 0, p0 = 0;
    if (valid) { d = __ldg(&deg[node]); p0 = __ldg(&start[node]); }

    float a[8] = {0.f,0.f,0.f,0.f,0.f,0.f,0.f,0.f};
    int i = 0;
    for (; i + 4 <= d; i += 4) {
        int n0 = __ldg(&col[p0 + i]);
        int n1 = __ldg(&col[p0 + i + 1]);
        int n2 = __ldg(&col[p0 + i + 2]);
        int n3 = __ldg(&col[p0 + i + 3]);
        uint4 v0 = __ldg((const uint4*)(y + (size_t)n0 * 40) + q);
        uint4 v1 = __ldg((const uint4*)(y + (size_t)n1 * 40) + q);
        uint4 v2 = __ldg((const uint4*)(y + (size_t)n2 * 40) + q);
        uint4 v3 = __ldg((const uint4*)(y + (size_t)n3 * 40) + q);
        acc8(a, v0); acc8(a, v1); acc8(a, v2); acc8(a, v3);
    }
    for (; i < d; i++) {
        int n0 = __ldg(&col[p0 + i]);
        uint4 v0 = __ldg((const uint4*)(y + (size_t)n0 * 40) + q);
        acc8(a, v0);
    }

    float v[8];
    float m = -FLT_MAX;
    if (valid) {
        const float iv = 1.0f / fmaxf((float)d, 1.0f);
        const float* zr = z + (size_t)node * 40 + q * 8;
        float4 zc0 = __ldg((const float4*)zr);
        float4 zc1 = __ldg((const float4*)(zr + 4));
        v[0] = a[0] * iv + zc0.x; v[1] = a[1] * iv + zc0.y;
        v[2] = a[2] * iv + zc0.z; v[3] = a[3] * iv + zc0.w;
        v[4] = a[4] * iv + zc1.x; v[5] = a[5] * iv + zc1.y;
        v[6] = a[6] * iv + zc1.z; v[7] = a[7] * iv + zc1.w;
#pragma unroll
        for (int k2 = 0; k2 < 8; k2++) m = fmaxf(m, v[k2]);
    }
    // 8-lane group reductions (offsets 1,2,4 stay within the group)
    m = fmaxf(m, __shfl_xor_sync(0xffffffffu, m, 1));
    m = fmaxf(m, __shfl_xor_sync(0xffffffffu, m, 2));
    m = fmaxf(m, __shfl_xor_sync(0xffffffffu, m, 4));

    float s = 0.f;
    if (valid) {
#pragma unroll
        for (int k2 = 0; k2 < 8; k2++) s += __expf(v[k2] - m);
    }
    s += __shfl_xor_sync(0xffffffffu, s, 1);
    s += __shfl_xor_sync(0xffffffffu, s, 2);
    s += __shfl_xor_sync(0xffffffffu, s, 4);

    if (valid) {
        const float l = m + __logf(s);
        float* orow = out + (size_t)node * 40 + q * 8;
        float4 r0, r1;
        r0.x = v[0] - l; r0.y = v[1] - l; r0.z = v[2] - l; r0.w = v[3] - l;
        r1.x = v[4] - l; r1.y = v[5] - l; r1.z = v[6] - l; r1.w = v[7] - l;
        *(float4*)orow       = r0;
        *(float4*)(orow + 4) = r1;
    }
}

// ---------------------------------------------------------------------------
// Tail: restore zero-state for next call
// ---------------------------------------------------------------------------
__global__ void tail_kernel(int* __restrict__ deg, int* __restrict__ cur,
                            int* __restrict__ pref, int n) {
    int i = blockIdx.x * blockDim.x + threadIdx.x;
    if (i < n) { deg[i] = 0; cur[i] = 0; }
    if (i < 1024) pref[i] = 0;
}

// ---------------------------------------------------------------------------
// kernel_launch — slot 4 is gemm_dual<64> (the ncu-profiled launch)
// ---------------------------------------------------------------------------
extern "C" void kernel_launch(void* const* d_in, const int* in_sizes, int n_in,
                              void* d_out, int out_size) {
    const float* x   = (const float*)d_in[0];
    const int*   ei  = (const int*)d_in[1];
    const float* Wl1 = (const float*)d_in[2];
    const float* Wr1 = (const float*)d_in[3];
    const float* b1  = (const float*)d_in[4];
    const float* Wl2 = (const float*)d_in[5];
    const float* Wr2 = (const float*)d_in[6];
    const float* b2  = (const float*)d_in[7];
    const float* Wl3 = (const float*)d_in[8];
    const float* Wr3 = (const float*)d_in[9];
    const float* b3  = (const float*)d_in[10];
    float* out = (float*)d_out;

    const int N = in_sizes[0] / 64;
    const int E = in_sizes[1] / 2;
    const int* src = ei;
    const int* dst = ei + E;

    int *deg, *cur, *start, *pref, *col;
    float *h1, *h2, *z;
    __half *y;
    cudaGetSymbolAddress((void**)&deg,   g_deg);
    cudaGetSymbolAddress((void**)&cur,   g_cur);
    cudaGetSymbolAddress((void**)&start, g_startArr);
    cudaGetSymbolAddress((void**)&pref,  g_pref);
    cudaGetSymbolAddress((void**)&col,   g_colArr);
    cudaGetSymbolAddress((void**)&h1,    g_h1);
    cudaGetSymbolAddress((void**)&h2,    g_h2);
    cudaGetSymbolAddress((void**)&y,     g_y);
    cudaGetSymbolAddress((void**)&z,     g_z);

    const int SMEM  = 48 * 1024;   // exactly 48KB: no opt-in needed
    const int nb    = (N + 1023) / 1024;
    const int edgeB = (E + 255) / 256;
    const int GB    = 592;
    const int gathB = (N + 31) / 32;

    hist_kernel<<<edgeB, 256>>>(dst, deg, E);                       // 1
    scan_kernel<<<nb, 1024>>>(deg, start, pref, N);                 // 2
    fill_kernel<<<edgeB, 256>>>(src, dst, start, cur, col, E);      // 3
    gemm_dual_kernel<64><<<GB, 256, SMEM>>>((const float4*)x,  Wl1, Wr1, b1, y, z, N);  // 4 (PROFILED)
    gather64_kernel<<<gathB, 256>>>(y, z, start, deg, col, h1, N);                      // 5
    gemm_dual_kernel<64><<<GB, 256, SMEM>>>((const float4*)h1, Wl2, Wr2, b2, y, z, N);  // 6
    gather64_kernel<<<gathB, 256>>>(y, z, start, deg, col, h2, N);                      // 7
    gemm_dual_kernel<40><<<GB, 256, SMEM>>>((const float4*)h2, Wl3, Wr3, b3, y, z, N);  // 8
    gather_lsm_kernel<<<gathB, 256>>>(y, z, start, deg, col, out, N);                   // 9
    tail_kernel<<<(N + 255) / 256, 256>>>(deg, cur, pref, N);       // 10
}

// round 13
// speedup vs baseline: 1.5745x; 1.5745x over previous
#include <cuda_runtime.h>
#include <cuda_fp16.h>
#include <math.h>
#include <float.h>

#define NMAX 100000
#define EMAX 1600000
#define CDIM 40

typedef unsigned long long u64;
typedef unsigned int u32;

// ---------------------------------------------------------------------------
// Scratch (device globals; tail kernel restores zero-state each call)
// ---------------------------------------------------------------------------
__device__ __align__(16) float  g_h1[NMAX * 64];
__device__ __align__(16) float  g_h2[NMAX * 64];
__device__ __align__(16) __half g_y [NMAX * 64];  // fp16 neighbor-transformed feats
__device__ __align__(16) float  g_z [NMAX * 64];  // fp32 self part (+bias)
__device__ int g_deg[NMAX];
__device__ int g_cur[NMAX];
__device__ int g_startArr[NMAX];
__device__ int g_pref[1024];
__device__ int g_colArr[EMAX];

// ---------------------------------------------------------------------------
// Launch 1: degree histogram (deg starts zeroed)
// ---------------------------------------------------------------------------
__global__ void hist_kernel(const int* __restrict__ dst, int* __restrict__ deg, int E) {
    int e = blockIdx.x * blockDim.x + threadIdx.x;
    if (e < E) atomicAdd(&deg[dst[e]], 1);
}

// ---------------------------------------------------------------------------
// Launch 2: single-pass exclusive scan, decoupled lookback (98 blocks, 1 wave)
// ---------------------------------------------------------------------------
__global__ void scan_kernel(const int* __restrict__ deg, int* __restrict__ start,
                            int* __restrict__ pref, int n) {
    const int t = threadIdx.x, b = blockIdx.x;
    const int gid = b * 1024 + t;
    const int v = (gid < n) ? deg[gid] : 0;
    const int lane = t & 31, w = t >> 5;
    int inc = v;
#pragma unroll
    for (int o = 1; o < 32; o <<= 1) {
        int u = __shfl_up_sync(0xffffffffu, inc, o);
        if (lane >= o) inc += u;
    }
    __shared__ int ws[32];
    __shared__ int sPref;
    if (lane == 31) ws[w] = inc;
    __syncthreads();
    if (t < 32) {
        int s = ws[t];
#pragma unroll
        for (int o = 1; o < 32; o <<= 1) {
            int u = __shfl_up_sync(0xffffffffu, s, o);
            if (t >= o) s += u;
        }
        ws[t] = s;
    }
    __syncthreads();
    const int offs  = (w > 0) ? ws[w - 1] : 0;
    const int total = ws[31];
    if (t == 0) {
        int prefix = 0;
        if (b > 0) {
            while ((prefix = atomicAdd(&pref[b], 0)) == 0) __nanosleep(40);
            prefix -= 1;
        }
        atomicExch(&pref[b + 1], prefix + total + 1);
        sPref = prefix;
    }
    __syncthreads();
    if (gid < n) start[gid] = sPref + offs + inc - v;
}

// ---------------------------------------------------------------------------
// Launch 3: CSR fill (cur starts zeroed)
// ---------------------------------------------------------------------------
__global__ void fill_kernel(const int* __restrict__ src, const int* __restrict__ dst,
                            const int* __restrict__ start, int* __restrict__ cur,
                            int* __restrict__ col, int E) {
    int e = blockIdx.x * blockDim.x + threadIdx.x;
    if (e < E) {
        int d = dst[e];
        int p = start[d] + atomicAdd(&cur[d], 1);
        col[p] = src[e];
    }
}

// ---------------------------------------------------------------------------
// mma.sync.m16n8k16 f16xf16 -> f32
// ---------------------------------------------------------------------------
__device__ __forceinline__ void mma16816(float* c, const u32* a, u32 b0, u32 b1) {
    asm volatile(
        "mma.sync.aligned.m16n8k16.row.col.f32.f16.f16.f32 "
        "{%0,%1,%2,%3}, {%4,%5,%6,%7}, {%8,%9}, {%0,%1,%2,%3};\n"
        : "+f"(c[0]), "+f"(c[1]), "+f"(c[2]), "+f"(c[3])
        : "r"(a[0]), "r"(a[1]), "r"(a[2]), "r"(a[3]), "r"(b0), "r"(b1));
}

// ---------------------------------------------------------------------------
// Tensor-core dual dense transform: y = fp16(x@Wl^T), z = x@Wr^T + b
// Tile = 64 nodes, 256 threads (8 warps).
// Combined weight Wc: rows [0,OUTS) = Wl (y), [OUTS,2*OUTS) = Wr (z).
// SMEM (27.6 KB): sW fp16[128][72-padded], sX fp16[64][72-padded].
//   Padding 72 halves/row => bank = (row*4 + lane%4) % 32: conflict-free for
//   both A-fragment and B-fragment LDS.32 patterns.
// Warp w: m-group = (w&3)*16 nodes, half = w>>2 (0=y, 1=z).
// Per warp: A frags 16 LDS.32 (reused over n), B frags 2/mma, NT*4 MMAs.
// ---------------------------------------------------------------------------
template <int OUTS>
__launch_bounds__(256)
__global__ void gemm_dual_mma_kernel(const float4* __restrict__ xin4,
                                     const float* __restrict__ Wl,
                                     const float* __restrict__ Wr,
                                     const float* __restrict__ bias,
                                     __half* __restrict__ y, float* __restrict__ z,
                                     int nN) {
    extern __shared__ __align__(16) unsigned char smem[];
    __half* sW = (__half*)smem;              // 128 * 72 halves = 18432 B
    __half* sX = (__half*)(smem + 18432);    //  64 * 72 halves =  9216 B

    const int tid = threadIdx.x;
    constexpr int NT = OUTS / 8;             // n-tiles per half: 8 or 5

    // Stage combined weights as fp16 (once per block)
    for (int idx = tid; idx < 2 * OUTS * 64; idx += 256) {
        int n = idx >> 6, k = idx & 63;
        float wv = (n < OUTS) ? Wl[n * 64 + k] : Wr[(n - OUTS) * 64 + k];
        sW[n * 72 + k] = __float2half(wv);
    }

    const int w    = tid >> 5;
    const int lane = tid & 31;
    const int grp  = lane >> 2;              // 0..7
    const int tig  = lane & 3;               // thread-in-group
    const int mg   = (w & 3) * 16;           // warp's m offset in tile
    const bool isZ = (w >= 4);
    const int nb0  = isZ ? OUTS : 0;

    const int gn = tid >> 2;                 // staging: node row 0..63
    const int q2 = tid & 3;                  // staging: 4 chunks of 4 floats

    const u32* sWu = (const u32*)sW;         // row stride 36 u32
    const u32* sXu = (const u32*)sX;

    const int nTiles = (nN + 63) >> 6;
    for (int t = blockIdx.x; t < nTiles; t += gridDim.x) {
        __syncthreads();                     // covers weight stage + sX reuse
        const int base = t << 6;

        // Stage 64 node rows as fp16 (each thread: 4 chunks of 4 floats)
        {
            const int node = base + gn;
            __half2 h[8];
#pragma unroll
            for (int c = 0; c < 4; c++) {
                float4 v = {0.f, 0.f, 0.f, 0.f};
                if (node < nN) v = __ldg(xin4 + (size_t)node * 16 + q2 * 4 + c);
                h[c * 2]     = __floats2half2_rn(v.x, v.y);
                h[c * 2 + 1] = __floats2half2_rn(v.z, v.w);
            }
            u32* dx = (u32*)(sX + gn * 72 + q2 * 16);
#pragma unroll
            for (int c = 0; c < 8; c++) dx[c] = ((u32*)h)[c];
        }
        __syncthreads();

        // Load A fragments: 4 k-steps x 4 regs
        u32 A[4][4];
        {
            const int r0 = mg + grp;
#pragma unroll
            for (int ks = 0; ks < 4; ks++) {
                A[ks][0] = sXu[r0 * 36 + ks * 8 + tig];
                A[ks][1] = sXu[(r0 + 8) * 36 + ks * 8 + tig];
                A[ks][2] = sXu[r0 * 36 + ks * 8 + 4 + tig];
                A[ks][3] = sXu[(r0 + 8) * 36 + ks * 8 + 4 + tig];
            }
        }

        // MMAs: NT n-tiles x 4 k-steps
        float acc[NT][4];
#pragma unroll
        for (int nt = 0; nt < NT; nt++) {
            acc[nt][0] = 0.f; acc[nt][1] = 0.f; acc[nt][2] = 0.f; acc[nt][3] = 0.f;
            const int nrow = nb0 + nt * 8 + grp;
#pragma unroll
            for (int ks = 0; ks < 4; ks++) {
                u32 b0 = sWu[nrow * 36 + ks * 8 + tig];
                u32 b1 = sWu[nrow * 36 + ks * 8 + 4 + tig];
                mma16816(acc[nt], A[ks], b0, b1);
            }
        }

        // Store: lane covers (m0, m0+8) x cols (n, n+1) per n-tile
        const int m0   = base + mg + grp;
        const int ncol = tig * 2;
        const bool ok0 = (m0 < nN);
        const bool ok1 = (m0 + 8 < nN);
        if (!isZ) {
#pragma unroll
            for (int nt = 0; nt < NT; nt++) {
                const int n = nt * 8 + ncol;
                if (ok0) *(__half2*)(y + (size_t)m0 * OUTS + n) =
                    __floats2half2_rn(acc[nt][0], acc[nt][1]);
                if (ok1) *(__half2*)(y + (size_t)(m0 + 8) * OUTS + n) =
                    __floats2half2_rn(acc[nt][2], acc[nt][3]);
            }
        } else {
#pragma unroll
            for (int nt = 0; nt < NT; nt++) {
                const int n = nt * 8 + ncol;
                const float b0v = __ldg(&bias[n]);
                const float b1v = __ldg(&bias[n + 1]);
                if (ok0) {
                    float2 r = {acc[nt][0] + b0v, acc[nt][1] + b1v};
                    *(float2*)(z + (size_t)m0 * OUTS + n) = r;
                }
                if (ok1) {
                    float2 r = {acc[nt][2] + b0v, acc[nt][3] + b1v};
                    *(float2*)(z + (size_t)(m0 + 8) * OUTS + n) = r;
                }
            }
        }
    }
}

// ---------------------------------------------------------------------------
// fp16 gather helpers
// ---------------------------------------------------------------------------
__device__ __forceinline__ void acc8(float* a, uint4 v) {
    float2 f;
    f = __half22float2(*(const __half2*)&v.x); a[0] += f.x; a[1] += f.y;
    f = __half22float2(*(const __half2*)&v.y); a[2] += f.x; a[3] += f.y;
    f = __half22float2(*(const __half2*)&v.z); a[4] += f.x; a[5] += f.y;
    f = __half22float2(*(const __half2*)&v.w); a[6] += f.x; a[7] += f.y;
}

// ---------------------------------------------------------------------------
// Gather (hidden layers, OUTS=64): out = relu(mean y + z)
// ---------------------------------------------------------------------------
__launch_bounds__(256)
__global__ void gather64_kernel(const __half* __restrict__ y,
                                const float* __restrict__ z,
                                const int* __restrict__ start,
                                const int* __restrict__ deg,
                                const int* __restrict__ col,
                                float* __restrict__ out, int nN) {
    const int node = blockIdx.x * 32 + (threadIdx.x >> 3);
    const int q = threadIdx.x & 7;
    if (node >= nN) return;

    const int d  = __ldg(&deg[node]);
    const int p0 = __ldg(&start[node]);

    float a[8] = {0.f,0.f,0.f,0.f,0.f,0.f,0.f,0.f};
    int i = 0;
    for (; i + 4 <= d; i += 4) {
        int n0 = __ldg(&col[p0 + i]);
        int n1 = __ldg(&col[p0 + i + 1]);
        int n2 = __ldg(&col[p0 + i + 2]);
        int n3 = __ldg(&col[p0 + i + 3]);
        uint4 v0 = __ldg((const uint4*)(y + (size_t)n0 * 64) + q);
        uint4 v1 = __ldg((const uint4*)(y + (size_t)n1 * 64) + q);
        uint4 v2 = __ldg((const uint4*)(y + (size_t)n2 * 64) + q);
        uint4 v3 = __ldg((const uint4*)(y + (size_t)n3 * 64) + q);
        acc8(a, v0); acc8(a, v1); acc8(a, v2); acc8(a, v3);
    }
    for (; i < d; i++) {
        int n0 = __ldg(&col[p0 + i]);
        uint4 v0 = __ldg((const uint4*)(y + (size_t)n0 * 64) + q);
        acc8(a, v0);
    }

    const float iv = 1.0f / fmaxf((float)d, 1.0f);
    const float* zr = z + (size_t)node * 64 + q * 8;
    float4 zc0 = __ldg((const float4*)zr);
    float4 zc1 = __ldg((const float4*)(zr + 4));
    float4 r0, r1;
    r0.x = fmaxf(a[0] * iv + zc0.x, 0.f); r0.y = fmaxf(a[1] * iv + zc0.y, 0.f);
    r0.z = fmaxf(a[2] * iv + zc0.z, 0.f); r0.w = fmaxf(a[3] * iv + zc0.w, 0.f);
    r1.x = fmaxf(a[4] * iv + zc1.x, 0.f); r1.y = fmaxf(a[5] * iv + zc1.y, 0.f);
    r1.z = fmaxf(a[6] * iv + zc1.z, 0.f); r1.w = fmaxf(a[7] * iv + zc1.w, 0.f);
    float* orow = out + (size_t)node * 64 + q * 8;
    *(float4*)orow       = r0;
    *(float4*)(orow + 4) = r1;
}

// ---------------------------------------------------------------------------
// Final gather + fused log_softmax (OUTS=40, 5 active chunks of 8)
// ---------------------------------------------------------------------------
__launch_bounds__(256)
__global__ void gather_lsm_kernel(const __half* __restrict__ y,
                                  const float* __restrict__ z,
                                  const int* __restrict__ start,
                                  const int* __restrict__ deg,
                                  const int* __restrict__ col,
                                  float* __restrict__ out, int nN) {
    const int node = blockIdx.x * 32 + (threadIdx.x >> 3);
    const int q = threadIdx.x & 7;
    const bool valid = (node < nN) && (q < 5);

    int d = 0, p0 = 0;
    if (valid) { d = __ldg(&deg[node]); p0 = __ldg(&start[node]); }

    float a[8] = {0.f,0.f,0.f,0.f,0.f,0.f,0.f,0.f};
    int i = 0;
    for (; i + 4 <= d; i += 4) {
        int n0 = __ldg(&col[p0 + i]);
        int n1 = __ldg(&col[p0 + i + 1]);
        int n2 = __ldg(&col[p0 + i + 2]);
        int n3 = __ldg(&col[p0 + i + 3]);
        uint4 v0 = __ldg((const uint4*)(y + (size_t)n0 * 40) + q);
        uint4 v1 = __ldg((const uint4*)(y + (size_t)n1 * 40) + q);
        uint4 v2 = __ldg((const uint4*)(y + (size_t)n2 * 40) + q);
        uint4 v3 = __ldg((const uint4*)(y + (size_t)n3 * 40) + q);
        acc8(a, v0); acc8(a, v1); acc8(a, v2); acc8(a, v3);
    }
    for (; i < d; i++) {
        int n0 = __ldg(&col[p0 + i]);
        uint4 v0 = __ldg((const uint4*)(y + (size_t)n0 * 40) + q);
        acc8(a, v0);
    }

    float v[8];
    float m = -FLT_MAX;
    if (valid) {
        const float iv = 1.0f / fmaxf((float)d, 1.0f);
        const float* zr = z + (size_t)node * 40 + q * 8;
        float4 zc0 = __ldg((const float4*)zr);
        float4 zc1 = __ldg((const float4*)(zr + 4));
        v[0] = a[0] * iv + zc0.x; v[1] = a[1] * iv + zc0.y;
        v[2] = a[2] * iv + zc0.z; v[3] = a[3] * iv + zc0.w;
        v[4] = a[4] * iv + zc1.x; v[5] = a[5] * iv + zc1.y;
        v[6] = a[6] * iv + zc1.z; v[7] = a[7] * iv + zc1.w;
#pragma unroll
        for (int k2 = 0; k2 < 8; k2++) m = fmaxf(m, v[k2]);
    }
    m = fmaxf(m, __shfl_xor_sync(0xffffffffu, m, 1));
    m = fmaxf(m, __shfl_xor_sync(0xffffffffu, m, 2));
    m = fmaxf(m, __shfl_xor_sync(0xffffffffu, m, 4));

    float s = 0.f;
    if (valid) {
#pragma unroll
        for (int k2 = 0; k2 < 8; k2++) s += __expf(v[k2] - m);
    }
    s += __shfl_xor_sync(0xffffffffu, s, 1);
    s += __shfl_xor_sync(0xffffffffu, s, 2);
    s += __shfl_xor_sync(0xffffffffu, s, 4);

    if (valid) {
        const float l = m + __logf(s);
        float* orow = out + (size_t)node * 40 + q * 8;
        float4 r0, r1;
        r0.x = v[0] - l; r0.y = v[1] - l; r0.z = v[2] - l; r0.w = v[3] - l;
        r1.x = v[4] - l; r1.y = v[5] - l; r1.z = v[6] - l; r1.w = v[7] - l;
        *(float4*)orow       = r0;
        *(float4*)(orow + 4) = r1;
    }
}

// ---------------------------------------------------------------------------
// Tail: restore zero-state for next call
// ---------------------------------------------------------------------------
__global__ void tail_kernel(int* __restrict__ deg, int* __restrict__ cur,
                            int* __restrict__ pref, int n) {
    int i = blockIdx.x * blockDim.x + threadIdx.x;
    if (i < n) { deg[i] = 0; cur[i] = 0; }
    if (i < 1024) pref[i] = 0;
}

// ---------------------------------------------------------------------------
// kernel_launch — slot 4 is gemm_dual_mma<64> (the ncu-profiled launch)
// ---------------------------------------------------------------------------
extern "C" void kernel_launch(void* const* d_in, const int* in_sizes, int n_in,
                              void* d_out, int out_size) {
    const float* x   = (const float*)d_in[0];
    const int*   ei  = (const int*)d_in[1];
    const float* Wl1 = (const float*)d_in[2];
    const float* Wr1 = (const float*)d_in[3];
    const float* b1  = (const float*)d_in[4];
    const float* Wl2 = (const float*)d_in[5];
    const float* Wr2 = (const float*)d_in[6];
    const float* b2  = (const float*)d_in[7];
    const float* Wl3 = (const float*)d_in[8];
    const float* Wr3 = (const float*)d_in[9];
    const float* b3  = (const float*)d_in[10];
    float* out = (float*)d_out;

    const int N = in_sizes[0] / 64;
    const int E = in_sizes[1] / 2;
    const int* src = ei;
    const int* dst = ei + E;

    int *deg, *cur, *start, *pref, *col;
    float *h1, *h2, *z;
    __half *y;
    cudaGetSymbolAddress((void**)&deg,   g_deg);
    cudaGetSymbolAddress((void**)&cur,   g_cur);
    cudaGetSymbolAddress((void**)&start, g_startArr);
    cudaGetSymbolAddress((void**)&pref,  g_pref);
    cudaGetSymbolAddress((void**)&col,   g_colArr);
    cudaGetSymbolAddress((void**)&h1,    g_h1);
    cudaGetSymbolAddress((void**)&h2,    g_h2);
    cudaGetSymbolAddress((void**)&y,     g_y);
    cudaGetSymbolAddress((void**)&z,     g_z);

    const int SMEM  = 18432 + 9216;   // 27.6 KB
    const int nb    = (N + 1023) / 1024;
    const int edgeB = (E + 255) / 256;
    const int GB    = 592;
    const int gathB = (N + 31) / 32;

    hist_kernel<<<edgeB, 256>>>(dst, deg, E);                       // 1
    scan_kernel<<<nb, 1024>>>(deg, start, pref, N);                 // 2
    fill_kernel<<<edgeB, 256>>>(src, dst, start, cur, col, E);      // 3
    gemm_dual_mma_kernel<64><<<GB, 256, SMEM>>>((const float4*)x,  Wl1, Wr1, b1, y, z, N);  // 4 (PROFILED)
    gather64_kernel<<<gathB, 256>>>(y, z, start, deg, col, h1, N);                          // 5
    gemm_dual_mma_kernel<64><<<GB, 256, SMEM>>>((const float4*)h1, Wl2, Wr2, b2, y, z, N);  // 6
    gather64_kernel<<<gathB, 256>>>(y, z, start, deg, col, h2, N);                          // 7
    gemm_dual_mma_kernel<40><<<GB, 256, SMEM>>>((const float4*)h2, Wl3, Wr3, b3, y, z, N);  // 8
    gather_lsm_kernel<<<gathB, 256>>>(y, z, start, deg, col, out, N);                       // 9
    tail_kernel<<<(N + 255) / 256, 256>>>(deg, cur, pref, N);       // 10
}

// round 14
// speedup vs baseline: 1.6519x; 1.0492x over previous
#include <cuda_runtime.h>
#include <cuda_fp16.h>
#include <math.h>
#include <float.h>

#define NMAX 100000
#define EMAX 1600000
#define CDIM 40

typedef unsigned long long u64;
typedef unsigned int u32;

// ---------------------------------------------------------------------------
// Scratch (device globals; tail kernel restores zero-state each call)
// All intermediates fp16: gemm quantizes inputs to fp16 anyway, so h1/h2
// cost zero extra precision; z-fp16 adds ~2e-4 on the self term.
// ---------------------------------------------------------------------------
__device__ __align__(16) __half g_h1[NMAX * 64];
__device__ __align__(16) __half g_h2[NMAX * 64];
__device__ __align__(16) __half g_y [NMAX * 64];
__device__ __align__(16) __half g_z [NMAX * 64];
__device__ int g_deg[NMAX];
__device__ int g_cur[NMAX];
__device__ int g_startArr[NMAX];
__device__ int g_pref[1024];
__device__ int g_colArr[EMAX];

// ---------------------------------------------------------------------------
// Launch 1: degree histogram (deg starts zeroed)
// ---------------------------------------------------------------------------
__global__ void hist_kernel(const int* __restrict__ dst, int* __restrict__ deg, int E) {
    int e = blockIdx.x * blockDim.x + threadIdx.x;
    if (e < E) atomicAdd(&deg[dst[e]], 1);
}

// ---------------------------------------------------------------------------
// Launch 2: single-pass exclusive scan, decoupled lookback (98 blocks, 1 wave)
// ---------------------------------------------------------------------------
__global__ void scan_kernel(const int* __restrict__ deg, int* __restrict__ start,
                            int* __restrict__ pref, int n) {
    const int t = threadIdx.x, b = blockIdx.x;
    const int gid = b * 1024 + t;
    const int v = (gid < n) ? deg[gid] : 0;
    const int lane = t & 31, w = t >> 5;
    int inc = v;
#pragma unroll
    for (int o = 1; o < 32; o <<= 1) {
        int u = __shfl_up_sync(0xffffffffu, inc, o);
        if (lane >= o) inc += u;
    }
    __shared__ int ws[32];
    __shared__ int sPref;
    if (lane == 31) ws[w] = inc;
    __syncthreads();
    if (t < 32) {
        int s = ws[t];
#pragma unroll
        for (int o = 1; o < 32; o <<= 1) {
            int u = __shfl_up_sync(0xffffffffu, s, o);
            if (t >= o) s += u;
        }
        ws[t] = s;
    }
    __syncthreads();
    const int offs  = (w > 0) ? ws[w - 1] : 0;
    const int total = ws[31];
    if (t == 0) {
        int prefix = 0;
        if (b > 0) {
            while ((prefix = atomicAdd(&pref[b], 0)) == 0) __nanosleep(40);
            prefix -= 1;
        }
        atomicExch(&pref[b + 1], prefix + total + 1);
        sPref = prefix;
    }
    __syncthreads();
    if (gid < n) start[gid] = sPref + offs + inc - v;
}

// ---------------------------------------------------------------------------
// mma.sync.m16n8k16 f16xf16 -> f32
// ---------------------------------------------------------------------------
__device__ __forceinline__ void mma16816(float* c, const u32* a, u32 b0, u32 b1) {
    asm volatile(
        "mma.sync.aligned.m16n8k16.row.col.f32.f16.f16.f32 "
        "{%0,%1,%2,%3}, {%4,%5,%6,%7}, {%8,%9}, {%0,%1,%2,%3};\n"
        : "+f"(c[0]), "+f"(c[1]), "+f"(c[2]), "+f"(c[3])
        : "r"(a[0]), "r"(a[1]), "r"(a[2]), "r"(a[3]), "r"(b0), "r"(b1));
}

// ---------------------------------------------------------------------------
// Tensor-core dual dense transform body: y = fp16(x@Wl^T), z = fp16(x@Wr^T + b)
// Tile = 64 nodes, 256 threads (8 warps); warp w: m = (w&3)*16, half = w>>2.
// SMEM 27.6KB: sW fp16[128][72], sX fp16[64][72] (72-pad: conflict-free frags).
// FP16IN: input rows already fp16 (h1/h2) -> raw uint4 copy staging.
// ---------------------------------------------------------------------------
template <int OUTS, bool FP16IN>
__device__ __forceinline__ void gemm_body(int bb, int gridB,
                                          const void* __restrict__ xin,
                                          const float* __restrict__ Wl,
                                          const float* __restrict__ Wr,
                                          const float* __restrict__ bias,
                                          __half* __restrict__ y,
                                          __half* __restrict__ z,
                                          int nN, unsigned char* smem) {
    __half* sW = (__half*)smem;              // 128 * 72 halves = 18432 B
    __half* sX = (__half*)(smem + 18432);    //  64 * 72 halves =  9216 B

    const int tid = threadIdx.x;
    constexpr int NT = OUTS / 8;

    for (int idx = tid; idx < 2 * OUTS * 64; idx += 256) {
        int n = idx >> 6, k = idx & 63;
        float wv = (n < OUTS) ? Wl[n * 64 + k] : Wr[(n - OUTS) * 64 + k];
        sW[n * 72 + k] = __float2half(wv);
    }

    const int w    = tid >> 5;
    const int lane = tid & 31;
    const int grp  = lane >> 2;
    const int tig  = lane & 3;
    const int mg   = (w & 3) * 16;
    const bool isZ = (w >= 4);
    const int nb0  = isZ ? OUTS : 0;

    const int gn = tid >> 2;                 // staging row 0..63
    const int q2 = tid & 3;

    const u32* sWu = (const u32*)sW;         // row stride 36 u32
    const u32* sXu = (const u32*)sX;

    const int nTiles = (nN + 63) >> 6;
    for (int t = bb; t < nTiles; t += gridB) {
        __syncthreads();
        const int base = t << 6;

        // Stage 64 node rows into sX
        {
            const int node = base + gn;
            if (FP16IN) {
                const uint4* rs = (const uint4*)xin + (size_t)node * 8 + q2 * 2;
                uint4 v0 = {0,0,0,0}, v1 = {0,0,0,0};
                if (node < nN) { v0 = __ldg(rs); v1 = __ldg(rs + 1); }
                uint4* dx = (uint4*)(sX + gn * 72 + q2 * 16);
                dx[0] = v0; dx[1] = v1;
            } else {
                const float4* rs = (const float4*)xin + (size_t)node * 16 + q2 * 4;
                __half2 h[8];
#pragma unroll
                for (int c = 0; c < 4; c++) {
                    float4 v = {0.f, 0.f, 0.f, 0.f};
                    if (node < nN) v = __ldg(rs + c);
                    h[c * 2]     = __floats2half2_rn(v.x, v.y);
                    h[c * 2 + 1] = __floats2half2_rn(v.z, v.w);
                }
                u32* dx = (u32*)(sX + gn * 72 + q2 * 16);
#pragma unroll
                for (int c = 0; c < 8; c++) dx[c] = ((u32*)h)[c];
            }
        }
        __syncthreads();

        u32 A[4][4];
        {
            const int r0 = mg + grp;
#pragma unroll
            for (int ks = 0; ks < 4; ks++) {
                A[ks][0] = sXu[r0 * 36 + ks * 8 + tig];
                A[ks][1] = sXu[(r0 + 8) * 36 + ks * 8 + tig];
                A[ks][2] = sXu[r0 * 36 + ks * 8 + 4 + tig];
                A[ks][3] = sXu[(r0 + 8) * 36 + ks * 8 + 4 + tig];
            }
        }

        float acc[NT][4];
#pragma unroll
        for (int nt = 0; nt < NT; nt++) {
            acc[nt][0] = 0.f; acc[nt][1] = 0.f; acc[nt][2] = 0.f; acc[nt][3] = 0.f;
            const int nrow = nb0 + nt * 8 + grp;
#pragma unroll
            for (int ks = 0; ks < 4; ks++) {
                u32 b0 = sWu[nrow * 36 + ks * 8 + tig];
                u32 b1 = sWu[nrow * 36 + ks * 8 + 4 + tig];
                mma16816(acc[nt], A[ks], b0, b1);
            }
        }

        const int m0   = base + mg + grp;
        const int ncol = tig * 2;
        const bool ok0 = (m0 < nN);
        const bool ok1 = (m0 + 8 < nN);
        if (!isZ) {
#pragma unroll
            for (int nt = 0; nt < NT; nt++) {
                const int n = nt * 8 + ncol;
                if (ok0) *(__half2*)(y + (size_t)m0 * OUTS + n) =
                    __floats2half2_rn(acc[nt][0], acc[nt][1]);
                if (ok1) *(__half2*)(y + (size_t)(m0 + 8) * OUTS + n) =
                    __floats2half2_rn(acc[nt][2], acc[nt][3]);
            }
        } else {
#pragma unroll
            for (int nt = 0; nt < NT; nt++) {
                const int n = nt * 8 + ncol;
                const float b0v = __ldg(&bias[n]);
                const float b1v = __ldg(&bias[n + 1]);
                if (ok0) *(__half2*)(z + (size_t)m0 * OUTS + n) =
                    __floats2half2_rn(acc[nt][0] + b0v, acc[nt][1] + b1v);
                if (ok1) *(__half2*)(z + (size_t)(m0 + 8) * OUTS + n) =
                    __floats2half2_rn(acc[nt][2] + b0v, acc[nt][3] + b1v);
            }
        }
    }
}

template <int OUTS, bool FP16IN>
__launch_bounds__(256)
__global__ void gemm_dual_mma_kernel(const void* __restrict__ xin,
                                     const float* __restrict__ Wl,
                                     const float* __restrict__ Wr,
                                     const float* __restrict__ bias,
                                     __half* __restrict__ y, __half* __restrict__ z,
                                     int nN) {
    extern __shared__ __align__(16) unsigned char smem[];
    gemm_body<OUTS, FP16IN>(blockIdx.x, gridDim.x, xin, Wl, Wr, bias, y, z, nN, smem);
}

// ---------------------------------------------------------------------------
// Launch 3: CSR fill (blocks [0,FB)) + layer-1 gemm (blocks [FB,FB+GB))
// Both depend only on scan; one launch hides fill behind gemm1.
// ---------------------------------------------------------------------------
__launch_bounds__(256)
__global__ void fill_gemm1_kernel(const int* __restrict__ src, const int* __restrict__ dst,
                                  const int* __restrict__ start, int* __restrict__ cur,
                                  int* __restrict__ col, int E, int FB,
                                  const float4* __restrict__ xin4,
                                  const float* __restrict__ Wl, const float* __restrict__ Wr,
                                  const float* __restrict__ bias,
                                  __half* __restrict__ y, __half* __restrict__ z,
                                  int nN, int GB) {
    extern __shared__ __align__(16) unsigned char smem[];
    if (blockIdx.x < FB) {
        int e = blockIdx.x * 256 + threadIdx.x;
        if (e < E) {
            int d = dst[e];
            int p = start[d] + atomicAdd(&cur[d], 1);
            col[p] = src[e];
        }
    } else {
        gemm_body<64, false>(blockIdx.x - FB, GB, xin4, Wl, Wr, bias, y, z, nN, smem);
    }
}

// ---------------------------------------------------------------------------
// fp16 helpers
// ---------------------------------------------------------------------------
__device__ __forceinline__ void acc8(float* a, uint4 v) {
    float2 f;
    f = __half22float2(*(const __half2*)&v.x); a[0] += f.x; a[1] += f.y;
    f = __half22float2(*(const __half2*)&v.y); a[2] += f.x; a[3] += f.y;
    f = __half22float2(*(const __half2*)&v.z); a[4] += f.x; a[5] += f.y;
    f = __half22float2(*(const __half2*)&v.w); a[6] += f.x; a[7] += f.y;
}

// ---------------------------------------------------------------------------
// Gather (hidden layers, 64-d): h = fp16(relu(mean y + z)), all fp16 rows 128B
// ---------------------------------------------------------------------------
__launch_bounds__(256)
__global__ void gather64_kernel(const __half* __restrict__ y,
                                const __half* __restrict__ z,
                                const int* __restrict__ start,
                                const int* __restrict__ deg,
                                const int* __restrict__ col,
                                __half* __restrict__ out, int nN) {
    const int node = blockIdx.x * 32 + (threadIdx.x >> 3);
    const int q = threadIdx.x & 7;
    if (node >= nN) return;

    const int d  = __ldg(&deg[node]);
    const int p0 = __ldg(&start[node]);

    float a[8] = {0.f,0.f,0.f,0.f,0.f,0.f,0.f,0.f};
    int i = 0;
    for (; i + 4 <= d; i += 4) {
        int n0 = __ldg(&col[p0 + i]);
        int n1 = __ldg(&col[p0 + i + 1]);
        int n2 = __ldg(&col[p0 + i + 2]);
        int n3 = __ldg(&col[p0 + i + 3]);
        uint4 v0 = __ldg((const uint4*)(y + (size_t)n0 * 64) + q);
        uint4 v1 = __ldg((const uint4*)(y + (size_t)n1 * 64) + q);
        uint4 v2 = __ldg((const uint4*)(y + (size_t)n2 * 64) + q);
        uint4 v3 = __ldg((const uint4*)(y + (size_t)n3 * 64) + q);
        acc8(a, v0); acc8(a, v1); acc8(a, v2); acc8(a, v3);
    }
    for (; i < d; i++) {
        int n0 = __ldg(&col[p0 + i]);
        uint4 v0 = __ldg((const uint4*)(y + (size_t)n0 * 64) + q);
        acc8(a, v0);
    }

    const float iv = 1.0f / fmaxf((float)d, 1.0f);
    uint4 zc = __ldg((const uint4*)(z + (size_t)node * 64) + q);
    float zf[8];
    {
        float2 f;
        f = __half22float2(*(const __half2*)&zc.x); zf[0] = f.x; zf[1] = f.y;
        f = __half22float2(*(const __half2*)&zc.y); zf[2] = f.x; zf[3] = f.y;
        f = __half22float2(*(const __half2*)&zc.z); zf[4] = f.x; zf[5] = f.y;
        f = __half22float2(*(const __half2*)&zc.w); zf[6] = f.x; zf[7] = f.y;
    }
    __half2 r[4];
#pragma unroll
    for (int c = 0; c < 4; c++) {
        float r0 = fmaxf(a[c*2]   * iv + zf[c*2],   0.f);
        float r1 = fmaxf(a[c*2+1] * iv + zf[c*2+1], 0.f);
        r[c] = __floats2half2_rn(r0, r1);
    }
    *((uint4*)(out + (size_t)node * 64) + q) = *(uint4*)r;
}

// ---------------------------------------------------------------------------
// Final gather + fused log_softmax (40-d; 5 active chunks of 8; fp32 out)
// ---------------------------------------------------------------------------
__launch_bounds__(256)
__global__ void gather_lsm_kernel(const __half* __restrict__ y,
                                  const __half* __restrict__ z,
                                  const int* __restrict__ start,
                                  const int* __restrict__ deg,
                                  const int* __restrict__ col,
                                  float* __restrict__ out, int nN) {
    const int node = blockIdx.x * 32 + (threadIdx.x >> 3);
    const int q = threadIdx.x & 7;
    const bool valid = (node < nN) && (q < 5);

    int d = 0, p0 = 0;
    if (valid) { d = __ldg(&deg[node]); p0 = __ldg(&start[node]); }

    float a[8] = {0.f,0.f,0.f,0.f,0.f,0.f,0.f,0.f};
    int i = 0;
    for (; i + 4 <= d; i += 4) {
        int n0 = __ldg(&col[p0 + i]);
        int n1 = __ldg(&col[p0 + i + 1]);
        int n2 = __ldg(&col[p0 + i + 2]);
        int n3 = __ldg(&col[p0 + i + 3]);
        uint4 v0 = __ldg((const uint4*)(y + (size_t)n0 * 40) + q);
        uint4 v1 = __ldg((const uint4*)(y + (size_t)n1 * 40) + q);
        uint4 v2 = __ldg((const uint4*)(y + (size_t)n2 * 40) + q);
        uint4 v3 = __ldg((const uint4*)(y + (size_t)n3 * 40) + q);
        acc8(a, v0); acc8(a, v1); acc8(a, v2); acc8(a, v3);
    }
    for (; i < d; i++) {
        int n0 = __ldg(&col[p0 + i]);
        uint4 v0 = __ldg((const uint4*)(y + (size_t)n0 * 40) + q);
        acc8(a, v0);
    }

    float v[8];
    float m = -FLT_MAX;
    if (valid) {
        const float iv = 1.0f / fmaxf((float)d, 1.0f);
        uint4 zc = __ldg((const uint4*)(z + (size_t)node * 40) + q);
        float zf[8];
        float2 f;
        f = __half22float2(*(const __half2*)&zc.x); zf[0] = f.x; zf[1] = f.y;
        f = __half22float2(*(const __half2*)&zc.y); zf[2] = f.x; zf[3] = f.y;
        f = __half22float2(*(const __half2*)&zc.z); zf[4] = f.x; zf[5] = f.y;
        f = __half22float2(*(const __half2*)&zc.w); zf[6] = f.x; zf[7] = f.y;
#pragma unroll
        for (int k2 = 0; k2 < 8; k2++) {
            v[k2] = a[k2] * iv + zf[k2];
            m = fmaxf(m, v[k2]);
        }
    }
    m = fmaxf(m, __shfl_xor_sync(0xffffffffu, m, 1));
    m = fmaxf(m, __shfl_xor_sync(0xffffffffu, m, 2));
    m = fmaxf(m, __shfl_xor_sync(0xffffffffu, m, 4));

    float s = 0.f;
    if (valid) {
#pragma unroll
        for (int k2 = 0; k2 < 8; k2++) s += __expf(v[k2] - m);
    }
    s += __shfl_xor_sync(0xffffffffu, s, 1);
    s += __shfl_xor_sync(0xffffffffu, s, 2);
    s += __shfl_xor_sync(0xffffffffu, s, 4);

    if (valid) {
        const float l = m + __logf(s);
        float* orow = out + (size_t)node * 40 + q * 8;
        float4 r0, r1;
        r0.x = v[0] - l; r0.y = v[1] - l; r0.z = v[2] - l; r0.w = v[3] - l;
        r1.x = v[4] - l; r1.y = v[5] - l; r1.z = v[6] - l; r1.w = v[7] - l;
        *(float4*)orow       = r0;
        *(float4*)(orow + 4) = r1;
    }
}

// ---------------------------------------------------------------------------
// Tail: restore zero-state for next call
// ---------------------------------------------------------------------------
__global__ void tail_kernel(int* __restrict__ deg, int* __restrict__ cur,
                            int* __restrict__ pref, int n) {
    int i = blockIdx.x * blockDim.x + threadIdx.x;
    if (i < n) { deg[i] = 0; cur[i] = 0; }
    if (i < 1024) pref[i] = 0;
}

// ---------------------------------------------------------------------------
// kernel_launch — slot 4 = gather64 layer 1 (the ncu-profiled launch)
// ---------------------------------------------------------------------------
extern "C" void kernel_launch(void* const* d_in, const int* in_sizes, int n_in,
                              void* d_out, int out_size) {
    const float* x   = (const float*)d_in[0];
    const int*   ei  = (const int*)d_in[1];
    const float* Wl1 = (const float*)d_in[2];
    const float* Wr1 = (const float*)d_in[3];
    const float* b1  = (const float*)d_in[4];
    const float* Wl2 = (const float*)d_in[5];
    const float* Wr2 = (const float*)d_in[6];
    const float* b2  = (const float*)d_in[7];
    const float* Wl3 = (const float*)d_in[8];
    const float* Wr3 = (const float*)d_in[9];
    const float* b3  = (const float*)d_in[10];
    float* out = (float*)d_out;

    const int N = in_sizes[0] / 64;
    const int E = in_sizes[1] / 2;
    const int* src = ei;
    const int* dst = ei + E;

    int *deg, *cur, *start, *pref, *col;
    __half *h1, *h2, *y, *z;
    cudaGetSymbolAddress((void**)&deg,   g_deg);
    cudaGetSymbolAddress((void**)&cur,   g_cur);
    cudaGetSymbolAddress((void**)&start, g_startArr);
    cudaGetSymbolAddress((void**)&pref,  g_pref);
    cudaGetSymbolAddress((void**)&col,   g_colArr);
    cudaGetSymbolAddress((void**)&h1,    g_h1);
    cudaGetSymbolAddress((void**)&h2,    g_h2);
    cudaGetSymbolAddress((void**)&y,     g_y);
    cudaGetSymbolAddress((void**)&z,     g_z);

    const int SMEM  = 18432 + 9216;   // 27.6 KB
    const int nb    = (N + 1023) / 1024;
    const int edgeB = (E + 255) / 256;
    const int GB    = 592;
    const int gathB = (N + 31) / 32;

    hist_kernel<<<edgeB, 256>>>(dst, deg, E);                       // 1
    scan_kernel<<<nb, 1024>>>(deg, start, pref, N);                 // 2
    fill_gemm1_kernel<<<edgeB + GB, 256, SMEM>>>(src, dst, start, cur, col, E, edgeB,
                                                 (const float4*)x, Wl1, Wr1, b1,
                                                 y, z, N, GB);      // 3 (fill + gemm1)
    gather64_kernel<<<gathB, 256>>>(y, z, start, deg, col, h1, N);  // 4 (PROFILED)
    gemm_dual_mma_kernel<64, true><<<GB, 256, SMEM>>>(h1, Wl2, Wr2, b2, y, z, N);  // 5
    gather64_kernel<<<gathB, 256>>>(y, z, start, deg, col, h2, N);  // 6
    gemm_dual_mma_kernel<40, true><<<GB, 256, SMEM>>>(h2, Wl3, Wr3, b3, y, z, N);  // 7
    gather_lsm_kernel<<<gathB, 256>>>(y, z, start, deg, col, out, N);              // 8
    tail_kernel<<<(N + 255) / 256, 256>>>(deg, cur, pref, N);       // 9
}